// round 14
// baseline (speedup 1.0000x reference)
#include <cuda_runtime.h>
#include <cstdint>

#define BB 64
#define NN 512
#define HH 128
#define NCOG 72
#define NRB 72

__device__ __align__(16) float g_wc[(size_t)BB * NN * NN];   // compacted w rows; pads stay BSS-zero
__device__ int      g_jlist[BB][NN];
__device__ int      g_jcnt[BB];
__device__ unsigned g_maxbits;

// ---------------------------------------------------------------------------
// Compaction + zero inactive output rows + reset max. Grid BB, 512 thr.
// ---------------------------------------------------------------------------
__global__ void __launch_bounds__(512) k_compact_zero(
    const float* __restrict__ mask,
    float*       __restrict__ out)
{
    int b = blockIdx.x;
    int j = threadIdx.x;
    if (b == 0 && j == 0) g_maxbits = 0u;

    bool act = (mask[b * NN + j] != 0.0f);
    unsigned ball = __ballot_sync(0xffffffffu, act);

    __shared__ int wcnt[16], wbase[16];
    int warp = j >> 5, lane = j & 31;
    if (lane == 0) wcnt[warp] = __popc(ball);
    __syncthreads();
    if (j == 0) {
        int s = 0;
        for (int w = 0; w < 16; w++) { wbase[w] = s; s += wcnt[w]; }
        g_jcnt[b] = s;
    }
    __syncthreads();
    if (act) {
        int pos = wbase[warp] + __popc(ball & ((1u << lane) - 1u));
        g_jlist[b][pos] = j;
    }

    // zero inactive rows (coalesced: 16 row-groups x 32 lanes, 32 iters)
    int rgrp = j >> 5;
    float4 z = make_float4(0.f, 0.f, 0.f, 0.f);
    for (int base = 0; base < NN; base += 16) {
        int row = base + rgrp;
        if (mask[b * NN + row] == 0.0f)
            ((float4*)(out + ((size_t)(b * NN + row)) * HH))[lane] = z;
    }
}

// ---------------------------------------------------------------------------
// Build compacted w rows: dense int4/float4 reads; DIRECT predicated STG.32
// to consecutive compact positions (order-preserving compaction => warp
// writes a contiguous range). No staging, no per-row barriers.
// 8 rows/block; s_pos built once, read as int4 (conflict-free LDS.128).
// ---------------------------------------------------------------------------
__global__ void __launch_bounds__(128) k_build_w(
    const int*   __restrict__ rmat,
    const float* __restrict__ dmat,
    const int*   __restrict__ cog,
    const float* __restrict__ domain)
{
    int b   = blockIdx.y;
    int cnt = g_jcnt[b];
    int ip_base = blockIdx.x * 8;
    if (ip_base >= cnt) return;

    __shared__ __align__(16) int s_pos[NN];
    __shared__ int s_rows[8];
    __shared__ float smax[4];
    int t = threadIdx.x;

    #pragma unroll
    for (int q = 0; q < 4; q++) s_pos[t + q * 128] = -1;
    __syncthreads();
    #pragma unroll
    for (int q = 0; q < 4; q++) {
        int jc = t + q * 128;
        if (jc < cnt) s_pos[g_jlist[b][jc]] = jc;
    }
    if (t < 8) {
        int ip = ip_base + t;
        s_rows[t] = (ip < cnt) ? g_jlist[b][ip] : -1;
    }
    __syncthreads();

    int nrows = min(8, cnt - ip_base);
    int j0 = t * 4;
    int4 pv = *(const int4*)(s_pos + j0);      // positions for j0..j0+3
    float lm = 0.f;

    for (int rr = 0; rr < nrows; rr++) {
        int i = s_rows[rr];
        size_t src = ((size_t)(b * NN + i)) * NN;

        int4   rv = *(const int4*)(rmat + src + j0);
        int4   cv = *(const int4*)(cog  + src + j0);
        float4 dv = *(const float4*)(dmat + src + j0);

        float w0 = fmaxf(__ldg(domain + cv.x * NRB + rv.x) - dv.x, 0.f);
        float w1 = fmaxf(__ldg(domain + cv.y * NRB + rv.y) - dv.y, 0.f);
        float w2 = fmaxf(__ldg(domain + cv.z * NRB + rv.z) - dv.z, 0.f);
        float w3 = fmaxf(__ldg(domain + cv.w * NRB + rv.w) - dv.w, 0.f);

        float* dst = g_wc + ((size_t)(b * NN + ip_base + rr)) * NN;
        if (pv.x >= 0) { dst[pv.x] = w0; lm = fmaxf(lm, w0); }
        if (pv.y >= 0) { dst[pv.y] = w1; lm = fmaxf(lm, w1); }
        if (pv.z >= 0) { dst[pv.z] = w2; lm = fmaxf(lm, w2); }
        if (pv.w >= 0) { dst[pv.w] = w3; lm = fmaxf(lm, w3); }
    }

    #pragma unroll
    for (int off = 16; off; off >>= 1)
        lm = fmaxf(lm, __shfl_xor_sync(0xffffffffu, lm, off));
    if ((t & 31) == 0) smax[t >> 5] = lm;
    __syncthreads();
    if (t == 0) {
        float bm = fmaxf(fmaxf(smax[0], smax[1]), fmaxf(smax[2], smax[3]));
        atomicMax(&g_maxbits, __float_as_uint(bm));
    }
}

// ---------------------------------------------------------------------------
// H-split compacted GEMM, software-pipelined. Block: 64i x 64h x full K,
// 256 threads, per-thread 4i x 4h. W staged via column-loads (4 coalesced
// LDG.32) + STS.128 into sWT[kk][iq*4]: lanes=kk -> banks 4kk mod 32,
// 8 lanes/phase cover all banks => conflict-free. Tile kt+1 prefetched into
// registers during compute of kt. 1/max in epilogue.
// ---------------------------------------------------------------------------
__global__ void __launch_bounds__(256, 3) k_gemm(
    const float* __restrict__ h_t,
    float*       __restrict__ out)
{
    int b   = blockIdx.y;
    int cnt = g_jcnt[b];
    int bx  = blockIdx.x;
    int it  = bx >> 1;
    int hs  = bx & 1;
    int ip0 = it * 64;
    if (ip0 >= cnt) return;
    int hoff = hs * 64;
    int nt = (cnt + 31) >> 5;

    int tid = threadIdx.x;
    int tx  = tid & 15;
    int ty  = tid >> 4;

    __shared__ __align__(16) float sWT[32][68];   // [kk][ii], 272B rows
    __shared__ __align__(16) float sH[32][64];
    __shared__ int s_jl[NN];
    __shared__ int s_il[64];

    #pragma unroll
    for (int q = 0; q < 2; q++) {
        int jc = tid + q * 256;
        s_jl[jc] = (jc < cnt) ? g_jlist[b][jc] : 0;
    }
    if (tid < 64) {
        int ip = ip0 + tid;
        s_il[tid] = (ip < cnt) ? g_jlist[b][ip] : 0;
    }
    __syncthreads();   // s_jl ready for first prefetch

    const float* hb = h_t + (size_t)b * HH + hoff;
    const float* wb = g_wc + ((size_t)b * NN + ip0) * NN;

    // Per-thread tile coords (constant across kt):
    //   W: two items e=tid, e=tid+256: kk = e&31 (lane), iq = e>>5 (0..15)
    //   H: two items: kk = e>>4, h4 = e&15
    int wkk0 = tid & 31,        wiq0 = tid >> 5;
    int wkk1 = wkk0,            wiq1 = (tid + 256) >> 5;
    int hkk0 = tid >> 4,        hh40 = tid & 15;
    int hkk1 = (tid + 256) >> 4, hh41 = tid & 15;

    float  wreg[8];
    float4 hreg[2];

    auto load_tile = [&](int kt) {
        int kc0 = kt * 32;
        const float* wc0 = wb + (size_t)(wiq0 * 4) * NN + kc0 + wkk0;
        const float* wc1 = wb + (size_t)(wiq1 * 4) * NN + kc0 + wkk1;
        #pragma unroll
        for (int c = 0; c < 4; c++) {
            wreg[c]     = (ip0 + wiq0 * 4 + c < cnt) ? wc0[(size_t)c * NN] : 0.f;
            wreg[4 + c] = (ip0 + wiq1 * 4 + c < cnt) ? wc1[(size_t)c * NN] : 0.f;
        }
        int j0 = s_jl[kc0 + hkk0];
        int j1 = s_jl[kc0 + hkk1];
        hreg[0] = *(const float4*)(hb + (size_t)j0 * (BB * HH) + hh40 * 4);
        hreg[1] = *(const float4*)(hb + (size_t)j1 * (BB * HH) + hh41 * 4);
    };

    load_tile(0);

    float acc[4][4];
    #pragma unroll
    for (int a = 0; a < 4; a++)
        #pragma unroll
        for (int c = 0; c < 4; c++) acc[a][c] = 0.f;

    for (int kt = 0; kt < nt; kt++) {
        // store staged tile
        *(float4*)(&sWT[wkk0][wiq0 * 4]) = make_float4(wreg[0], wreg[1], wreg[2], wreg[3]);
        *(float4*)(&sWT[wkk1][wiq1 * 4]) = make_float4(wreg[4], wreg[5], wreg[6], wreg[7]);
        *(float4*)(&sH[hkk0][hh40 * 4]) = hreg[0];
        *(float4*)(&sH[hkk1][hh41 * 4]) = hreg[1];
        __syncthreads();

        if (kt + 1 < nt) load_tile(kt + 1);   // LDG in flight during compute

        #pragma unroll
        for (int kk = 0; kk < 32; kk++) {
            float4 w4 = *(const float4*)(&sWT[kk][ty * 4]);
            float4 hv = *(const float4*)(&sH[kk][tx * 4]);
            acc[0][0] = fmaf(w4.x, hv.x, acc[0][0]);
            acc[0][1] = fmaf(w4.x, hv.y, acc[0][1]);
            acc[0][2] = fmaf(w4.x, hv.z, acc[0][2]);
            acc[0][3] = fmaf(w4.x, hv.w, acc[0][3]);
            acc[1][0] = fmaf(w4.y, hv.x, acc[1][0]);
            acc[1][1] = fmaf(w4.y, hv.y, acc[1][1]);
            acc[1][2] = fmaf(w4.y, hv.z, acc[1][2]);
            acc[1][3] = fmaf(w4.y, hv.w, acc[1][3]);
            acc[2][0] = fmaf(w4.z, hv.x, acc[2][0]);
            acc[2][1] = fmaf(w4.z, hv.y, acc[2][1]);
            acc[2][2] = fmaf(w4.z, hv.z, acc[2][2]);
            acc[2][3] = fmaf(w4.z, hv.w, acc[2][3]);
            acc[3][0] = fmaf(w4.w, hv.x, acc[3][0]);
            acc[3][1] = fmaf(w4.w, hv.y, acc[3][1]);
            acc[3][2] = fmaf(w4.w, hv.z, acc[3][2]);
            acc[3][3] = fmaf(w4.w, hv.w, acc[3][3]);
        }
        __syncthreads();   // readers done before next store
    }

    float inv = 1.0f / __uint_as_float(g_maxbits);
    #pragma unroll
    for (int a = 0; a < 4; a++) {
        int ipl = ty * 4 + a;
        if (ip0 + ipl < cnt) {
            int i = s_il[ipl];
            float* op = out + ((size_t)(b * NN + i)) * HH + hoff;
            *(float4*)(op + tx * 4) = make_float4(acc[a][0] * inv, acc[a][1] * inv,
                                                  acc[a][2] * inv, acc[a][3] * inv);
        }
    }
}

// ---------------------------------------------------------------------------
extern "C" void kernel_launch(void* const* d_in, const int* in_sizes, int n_in,
                              void* d_out, int out_size)
{
    const float* h_t    = (const float*)d_in[0];
    const int*   r_mat  = (const int*)  d_in[1];
    const float* d_mat  = (const float*)d_in[2];
    const float* mask   = (const float*)d_in[3];
    const int*   cog    = (const int*)  d_in[4];
    const float* domain = (const float*)d_in[5];
    float* out = (float*)d_out;

    k_compact_zero<<<BB, 512>>>(mask, out);
    dim3 g1(NN / 8, BB);
    k_build_w<<<g1, 128>>>(r_mat, d_mat, cog, domain);
    dim3 g2((NN / 64) * 2, BB);          // (i-tile, h-half) pairs
    k_gemm<<<g2, 256>>>(h_t, out);
}

// round 15
// speedup vs baseline: 1.1276x; 1.1276x over previous
#include <cuda_runtime.h>
#include <cstdint>

#define BB 64
#define NN 512
#define HH 128
#define NCOG 72
#define NRB 72

__device__ __align__(16) float g_wc[(size_t)BB * NN * NN];   // compacted w rows (~17MB, L2-resident)
__device__ int      g_jlist[BB][NN];
__device__ int      g_jcnt[BB];
__device__ unsigned g_maxbits;

// ---------------------------------------------------------------------------
__global__ void k_compact(const float* __restrict__ mask) {
    int b = blockIdx.x;
    int j = threadIdx.x;
    if (b == 0 && j == 0) g_maxbits = 0u;

    bool act = (mask[b * NN + j] != 0.0f);
    unsigned ball = __ballot_sync(0xffffffffu, act);

    __shared__ int wcnt[16], wbase[16];
    int warp = j >> 5, lane = j & 31;
    if (lane == 0) wcnt[warp] = __popc(ball);
    __syncthreads();
    if (j == 0) {
        int s = 0;
        for (int w = 0; w < 16; w++) { wbase[w] = s; s += wcnt[w]; }
        g_jcnt[b] = s;
    }
    __syncthreads();
    if (act) {
        int pos = wbase[warp] + __popc(ball & ((1u << lane) - 1u));
        g_jlist[b][pos] = j;
    }
}

// ---------------------------------------------------------------------------
// Zero inactive output rows (active rows fully written by the GEMM).
// ---------------------------------------------------------------------------
__global__ void __launch_bounds__(256) k_zero_inactive(
    const float* __restrict__ mask,
    float*       __restrict__ out)
{
    int b  = blockIdx.y;
    int rr = threadIdx.x >> 5;
    int c  = threadIdx.x & 31;
    int i  = blockIdx.x * 8 + rr;
    if (mask[b * NN + i] != 0.0f) return;
    float4* po = (float4*)(out + ((size_t)(b * NN + i)) * HH);
    po[c] = make_float4(0.f, 0.f, 0.f, 0.f);
}

// ---------------------------------------------------------------------------
// Build compacted w rows (R13 staged version: dense int4/float4 reads, smem
// scatter staging, compact float4 writes; 8 rows/block; s_pos built once).
// ---------------------------------------------------------------------------
__global__ void __launch_bounds__(128) k_build_w(
    const int*   __restrict__ rmat,
    const float* __restrict__ dmat,
    const int*   __restrict__ cog,
    const float* __restrict__ domain)
{
    int b   = blockIdx.y;
    int cnt = g_jcnt[b];
    int ip_base = blockIdx.x * 8;
    if (ip_base >= cnt) return;

    __shared__ int s_pos[NN];
    __shared__ __align__(16) float s_stage[NN];
    __shared__ int s_rows[8];
    __shared__ float smax[4];
    int t = threadIdx.x;

    #pragma unroll
    for (int q = 0; q < 4; q++) {
        s_pos[t + q * 128]   = -1;
        s_stage[t + q * 128] = 0.f;
    }
    __syncthreads();
    #pragma unroll
    for (int q = 0; q < 4; q++) {
        int jc = t + q * 128;
        if (jc < cnt) s_pos[g_jlist[b][jc]] = jc;
    }
    if (t < 8) {
        int ip = ip_base + t;
        s_rows[t] = (ip < cnt) ? g_jlist[b][ip] : -1;
    }
    __syncthreads();

    int cnt32 = (cnt + 31) & ~31;
    int nrows = min(8, cnt - ip_base);
    int j0 = t * 4;
    float lm = 0.f;

    for (int rr = 0; rr < nrows; rr++) {
        int i = s_rows[rr];
        size_t src = ((size_t)(b * NN + i)) * NN;

        int4   rv = *(const int4*)(rmat + src + j0);
        int4   cv = *(const int4*)(cog  + src + j0);
        float4 dv = *(const float4*)(dmat + src + j0);

        float w0 = fmaxf(__ldg(domain + cv.x * NRB + rv.x) - dv.x, 0.f);
        float w1 = fmaxf(__ldg(domain + cv.y * NRB + rv.y) - dv.y, 0.f);
        float w2 = fmaxf(__ldg(domain + cv.z * NRB + rv.z) - dv.z, 0.f);
        float w3 = fmaxf(__ldg(domain + cv.w * NRB + rv.w) - dv.w, 0.f);

        int p0 = s_pos[j0 + 0], p1 = s_pos[j0 + 1], p2 = s_pos[j0 + 2], p3 = s_pos[j0 + 3];
        if (p0 >= 0) { s_stage[p0] = w0; lm = fmaxf(lm, w0); }
        if (p1 >= 0) { s_stage[p1] = w1; lm = fmaxf(lm, w1); }
        if (p2 >= 0) { s_stage[p2] = w2; lm = fmaxf(lm, w2); }
        if (p3 >= 0) { s_stage[p3] = w3; lm = fmaxf(lm, w3); }
        __syncthreads();

        size_t dst = ((size_t)(b * NN + ip_base + rr)) * NN;
        if (j0 < cnt32)
            *(float4*)(g_wc + dst + j0) = *(const float4*)(s_stage + j0);
        __syncthreads();
    }

    #pragma unroll
    for (int off = 16; off; off >>= 1)
        lm = fmaxf(lm, __shfl_xor_sync(0xffffffffu, lm, off));
    if ((t & 31) == 0) smax[t >> 5] = lm;
    __syncthreads();
    if (t == 0) {
        float bm = fmaxf(fmaxf(smax[0], smax[1]), fmaxf(smax[2], smax[3]));
        atomicMax(&g_maxbits, __float_as_uint(bm));
    }
}

// ---------------------------------------------------------------------------
// H-split compacted GEMM (R13 structure). Block: 64i x 64h x full K,
// 256 threads, per-thread 4i x 4h. SINGLE CHANGE vs R13: W-tile staging is
// now column-load + STS.128 (conflict-free) instead of the 4-way-conflicted
// transpose STS.32. Lane=kk -> sWT row kk, bank base 4*kk: each 8-lane
// phase covers all 32 banks. Global side: per c, lanes read consecutive
// addresses (128B coalesced rows of g_wc).
// ---------------------------------------------------------------------------
__global__ void __launch_bounds__(256, 4) k_gemm(
    const float* __restrict__ h_t,
    float*       __restrict__ out)
{
    int b   = blockIdx.y;
    int cnt = g_jcnt[b];
    int bx  = blockIdx.x;
    int it  = bx >> 1;
    int hs  = bx & 1;
    int ip0 = it * 64;
    if (ip0 >= cnt) return;
    int hoff = hs * 64;
    int nt = (cnt + 31) >> 5;

    int tid = threadIdx.x;
    int tx  = tid & 15;                  // h quad within 64
    int ty  = tid >> 4;                  // i quad (0..15)

    __shared__ __align__(16) float sWT[32][68];   // [kk][ii], 272B rows
    __shared__ __align__(16) float sH[32][64];
    __shared__ int s_jl[NN];
    __shared__ int s_il[64];

    #pragma unroll
    for (int q = 0; q < 2; q++) {
        int jc = tid + q * 256;
        s_jl[jc] = (jc < cnt) ? g_jlist[b][jc] : 0;
    }
    if (tid < 64) {
        int ip = ip0 + tid;
        s_il[tid] = (ip < cnt) ? g_jlist[b][ip] : 0;
    }

    float acc[4][4];
    #pragma unroll
    for (int a = 0; a < 4; a++)
        #pragma unroll
        for (int c = 0; c < 4; c++) acc[a][c] = 0.f;

    const float* hb = h_t + (size_t)b * HH + hoff;
    const float* wb = g_wc + ((size_t)b * NN + ip0) * NN;

    // W staging coords: e = tid, tid+256 -> kk = e&31 (lane), iq = e>>5 (0..15)
    int wkk = tid & 31;
    int wiq0 = tid >> 5;            // 0..7
    int wiq1 = (tid + 256) >> 5;    // 8..15

    for (int kt = 0; kt < nt; kt++) {
        int kc0 = kt * 32;
        __syncthreads();

        // W tile 64x32: per thread 2 columns of 4 ii, conflict-free STS.128.
        {
            const float* wc0 = wb + (size_t)(wiq0 * 4) * NN + kc0 + wkk;
            const float* wc1 = wb + (size_t)(wiq1 * 4) * NN + kc0 + wkk;
            float v0[4], v1[4];
            #pragma unroll
            for (int c = 0; c < 4; c++) {
                v0[c] = (ip0 + wiq0 * 4 + c < cnt) ? wc0[(size_t)c * NN] : 0.f;
                v1[c] = (ip0 + wiq1 * 4 + c < cnt) ? wc1[(size_t)c * NN] : 0.f;
            }
            *(float4*)(&sWT[wkk][wiq0 * 4]) = make_float4(v0[0], v0[1], v0[2], v0[3]);
            *(float4*)(&sWT[wkk][wiq1 * 4]) = make_float4(v1[0], v1[1], v1[2], v1[3]);
        }
        // H tile 32x64 gathered rows: 512 float4, 2/thread (256B-coalesced).
        #pragma unroll
        for (int rep = 0; rep < 2; rep++) {
            int e  = rep * 256 + tid;
            int kk = e >> 4;
            int h4 = e & 15;
            int j  = s_jl[kc0 + kk];
            float4 hv = *(const float4*)(hb + (size_t)j * (BB * HH) + h4 * 4);
            *(float4*)(&sH[kk][h4 * 4]) = hv;
        }
        __syncthreads();

        #pragma unroll
        for (int kk = 0; kk < 32; kk++) {
            float4 w4 = *(const float4*)(&sWT[kk][ty * 4]);   // broadcast, 1 wf
            float4 hv = *(const float4*)(&sH[kk][tx * 4]);    // 2 wf
            acc[0][0] = fmaf(w4.x, hv.x, acc[0][0]);
            acc[0][1] = fmaf(w4.x, hv.y, acc[0][1]);
            acc[0][2] = fmaf(w4.x, hv.z, acc[0][2]);
            acc[0][3] = fmaf(w4.x, hv.w, acc[0][3]);
            acc[1][0] = fmaf(w4.y, hv.x, acc[1][0]);
            acc[1][1] = fmaf(w4.y, hv.y, acc[1][1]);
            acc[1][2] = fmaf(w4.y, hv.z, acc[1][2]);
            acc[1][3] = fmaf(w4.y, hv.w, acc[1][3]);
            acc[2][0] = fmaf(w4.z, hv.x, acc[2][0]);
            acc[2][1] = fmaf(w4.z, hv.y, acc[2][1]);
            acc[2][2] = fmaf(w4.z, hv.z, acc[2][2]);
            acc[2][3] = fmaf(w4.z, hv.w, acc[2][3]);
            acc[3][0] = fmaf(w4.w, hv.x, acc[3][0]);
            acc[3][1] = fmaf(w4.w, hv.y, acc[3][1]);
            acc[3][2] = fmaf(w4.w, hv.z, acc[3][2]);
            acc[3][3] = fmaf(w4.w, hv.w, acc[3][3]);
        }
    }

    float inv = 1.0f / __uint_as_float(g_maxbits);
    #pragma unroll
    for (int a = 0; a < 4; a++) {
        int ipl = ty * 4 + a;
        if (ip0 + ipl < cnt) {
            int i = s_il[ipl];
            float* op = out + ((size_t)(b * NN + i)) * HH + hoff;
            *(float4*)(op + tx * 4) = make_float4(acc[a][0] * inv, acc[a][1] * inv,
                                                  acc[a][2] * inv, acc[a][3] * inv);
        }
    }
}

// ---------------------------------------------------------------------------
extern "C" void kernel_launch(void* const* d_in, const int* in_sizes, int n_in,
                              void* d_out, int out_size)
{
    const float* h_t    = (const float*)d_in[0];
    const int*   r_mat  = (const int*)  d_in[1];
    const float* d_mat  = (const float*)d_in[2];
    const float* mask   = (const float*)d_in[3];
    const int*   cog    = (const int*)  d_in[4];
    const float* domain = (const float*)d_in[5];
    float* out = (float*)d_out;

    k_compact<<<BB, NN>>>(mask);
    dim3 gz(NN / 8, BB);
    k_zero_inactive<<<gz, 256>>>(mask, out);
    dim3 g1(NN / 8, BB);
    k_build_w<<<g1, 128>>>(r_mat, d_mat, cog, domain);
    dim3 g2((NN / 64) * 2, BB);          // (i-tile, h-half) pairs
    k_gemm<<<g2, 256>>>(h_t, out);
}

// round 16
// speedup vs baseline: 1.1631x; 1.0315x over previous
#include <cuda_runtime.h>
#include <cstdint>

#define BB 64
#define NN 512
#define HH 128
#define NCOG 72
#define NRB 72

__device__ __align__(16) float g_wc[(size_t)BB * NN * NN];   // compacted w rows (~17MB, L2-resident)
__device__ int      g_jlist[BB][NN];
__device__ int      g_jcnt[BB];
__device__ unsigned g_maxbits;

// ---------------------------------------------------------------------------
__global__ void k_compact(const float* __restrict__ mask) {
    int b = blockIdx.x;
    int j = threadIdx.x;
    if (b == 0 && j == 0) g_maxbits = 0u;

    bool act = (mask[b * NN + j] != 0.0f);
    unsigned ball = __ballot_sync(0xffffffffu, act);

    __shared__ int wcnt[16], wbase[16];
    int warp = j >> 5, lane = j & 31;
    if (lane == 0) wcnt[warp] = __popc(ball);
    __syncthreads();
    if (j == 0) {
        int s = 0;
        for (int w = 0; w < 16; w++) { wbase[w] = s; s += wcnt[w]; }
        g_jcnt[b] = s;
    }
    __syncthreads();
    if (act) {
        int pos = wbase[warp] + __popc(ball & ((1u << lane) - 1u));
        g_jlist[b][pos] = j;
    }
}

// ---------------------------------------------------------------------------
__global__ void __launch_bounds__(256) k_zero_inactive(
    const float* __restrict__ mask,
    float*       __restrict__ out)
{
    int b  = blockIdx.y;
    int rr = threadIdx.x >> 5;
    int c  = threadIdx.x & 31;
    int i  = blockIdx.x * 8 + rr;
    if (mask[b * NN + i] != 0.0f) return;
    float4* po = (float4*)(out + ((size_t)(b * NN + i)) * HH);
    po[c] = make_float4(0.f, 0.f, 0.f, 0.f);
}

// ---------------------------------------------------------------------------
// Build compacted w rows, ROW-PIPELINED: row rr+1's dense int4/float4 loads
// issue before row rr's stage/copy (LDG latency hidden behind the barriers).
// ---------------------------------------------------------------------------
__global__ void __launch_bounds__(128) k_build_w(
    const int*   __restrict__ rmat,
    const float* __restrict__ dmat,
    const int*   __restrict__ cog,
    const float* __restrict__ domain)
{
    int b   = blockIdx.y;
    int cnt = g_jcnt[b];
    int ip_base = blockIdx.x * 8;
    if (ip_base >= cnt) return;

    __shared__ int s_pos[NN];
    __shared__ __align__(16) float s_stage[NN];
    __shared__ int s_rows[8];
    __shared__ float smax[4];
    int t = threadIdx.x;

    #pragma unroll
    for (int q = 0; q < 4; q++) {
        s_pos[t + q * 128]   = -1;
        s_stage[t + q * 128] = 0.f;
    }
    __syncthreads();
    #pragma unroll
    for (int q = 0; q < 4; q++) {
        int jc = t + q * 128;
        if (jc < cnt) s_pos[g_jlist[b][jc]] = jc;
    }
    if (t < 8) {
        int ip = ip_base + t;
        s_rows[t] = (ip < cnt) ? g_jlist[b][ip] : -1;
    }
    __syncthreads();

    int cnt32 = (cnt + 31) & ~31;
    int nrows = min(8, cnt - ip_base);
    int j0 = t * 4;
    float lm = 0.f;

    // preload row 0
    int4 rvA, cvA; float4 dvA;
    {
        size_t src = ((size_t)(b * NN + s_rows[0])) * NN;
        rvA = *(const int4*)(rmat + src + j0);
        cvA = *(const int4*)(cog  + src + j0);
        dvA = *(const float4*)(dmat + src + j0);
    }

    for (int rr = 0; rr < nrows; rr++) {
        int4 rvB, cvB; float4 dvB;
        if (rr + 1 < nrows) {                 // issue next row's loads EARLY
            size_t srcB = ((size_t)(b * NN + s_rows[rr + 1])) * NN;
            rvB = *(const int4*)(rmat + srcB + j0);
            cvB = *(const int4*)(cog  + srcB + j0);
            dvB = *(const float4*)(dmat + srcB + j0);
        }

        float w0 = fmaxf(__ldg(domain + cvA.x * NRB + rvA.x) - dvA.x, 0.f);
        float w1 = fmaxf(__ldg(domain + cvA.y * NRB + rvA.y) - dvA.y, 0.f);
        float w2 = fmaxf(__ldg(domain + cvA.z * NRB + rvA.z) - dvA.z, 0.f);
        float w3 = fmaxf(__ldg(domain + cvA.w * NRB + rvA.w) - dvA.w, 0.f);

        int p0 = s_pos[j0 + 0], p1 = s_pos[j0 + 1], p2 = s_pos[j0 + 2], p3 = s_pos[j0 + 3];
        if (p0 >= 0) { s_stage[p0] = w0; lm = fmaxf(lm, w0); }
        if (p1 >= 0) { s_stage[p1] = w1; lm = fmaxf(lm, w1); }
        if (p2 >= 0) { s_stage[p2] = w2; lm = fmaxf(lm, w2); }
        if (p3 >= 0) { s_stage[p3] = w3; lm = fmaxf(lm, w3); }
        __syncthreads();

        size_t dst = ((size_t)(b * NN + ip_base + rr)) * NN;
        if (j0 < cnt32)
            *(float4*)(g_wc + dst + j0) = *(const float4*)(s_stage + j0);
        __syncthreads();

        rvA = rvB; cvA = cvB; dvA = dvB;
    }

    #pragma unroll
    for (int off = 16; off; off >>= 1)
        lm = fmaxf(lm, __shfl_xor_sync(0xffffffffu, lm, off));
    if ((t & 31) == 0) smax[t >> 5] = lm;
    __syncthreads();
    if (t == 0) {
        float bm = fmaxf(fmaxf(smax[0], smax[1]), fmaxf(smax[2], smax[3]));
        atomicMax(&g_maxbits, __float_as_uint(bm));
    }
}

// ---------------------------------------------------------------------------
// H-split compacted GEMM, DOUBLE-BUFFERED. Block: 64i x 64h x full K,
// 256 threads, per-thread 4i x 4h. H tiles via cp.async (16B, direct);
// W tiles via early LDG column-loads + conflict-free STS.128 after compute.
// One barrier per k-tile; GMEM latency hidden behind the 32-kk FFMA block.
// ---------------------------------------------------------------------------
__global__ void __launch_bounds__(256, 4) k_gemm(
    const float* __restrict__ h_t,
    float*       __restrict__ out)
{
    int b   = blockIdx.y;
    int cnt = g_jcnt[b];
    int bx  = blockIdx.x;
    int it  = bx >> 1;
    int hs  = bx & 1;
    int ip0 = it * 64;
    if (ip0 >= cnt) return;
    int hoff = hs * 64;
    int nt = (cnt + 31) >> 5;

    int tid = threadIdx.x;
    int tx  = tid & 15;
    int ty  = tid >> 4;

    __shared__ __align__(16) float sWT[2][32][68];
    __shared__ __align__(16) float sH[2][32][64];
    __shared__ int s_jl[NN];
    __shared__ int s_il[64];

    #pragma unroll
    for (int q = 0; q < 2; q++) {
        int jc = tid + q * 256;
        s_jl[jc] = (jc < cnt) ? g_jlist[b][jc] : 0;
    }
    if (tid < 64) {
        int ip = ip0 + tid;
        s_il[tid] = (ip < cnt) ? g_jlist[b][ip] : 0;
    }
    __syncthreads();   // s_jl ready

    const float* hb = h_t + (size_t)b * HH + hoff;
    const float* wb = g_wc + ((size_t)b * NN + ip0) * NN;

    // per-thread staging coords
    int wkk  = tid & 31;
    int wiq0 = tid >> 5;             // 0..7
    int wiq1 = (tid + 256) >> 5;     // 8..15
    int hkk0 = tid >> 4,  hh4 = tid & 15;
    int hkk1 = (tid + 256) >> 4;

    float wreg[8];

    auto cp_h = [&](int kt, int buf) {
        int kc0 = kt * 32;
        int j0 = s_jl[kc0 + hkk0];
        int j1 = s_jl[kc0 + hkk1];
        uint32_t d0 = (uint32_t)__cvta_generic_to_shared(&sH[buf][hkk0][hh4 * 4]);
        uint32_t d1 = (uint32_t)__cvta_generic_to_shared(&sH[buf][hkk1][hh4 * 4]);
        const float* s0 = hb + (size_t)j0 * (BB * HH) + hh4 * 4;
        const float* s1 = hb + (size_t)j1 * (BB * HH) + hh4 * 4;
        asm volatile("cp.async.ca.shared.global [%0], [%1], 16;\n" :: "r"(d0), "l"(s0));
        asm volatile("cp.async.ca.shared.global [%0], [%1], 16;\n" :: "r"(d1), "l"(s1));
        asm volatile("cp.async.commit_group;\n");
    };
    auto ldg_w = [&](int kt) {
        int kc0 = kt * 32;
        const float* wc0 = wb + (size_t)(wiq0 * 4) * NN + kc0 + wkk;
        const float* wc1 = wb + (size_t)(wiq1 * 4) * NN + kc0 + wkk;
        #pragma unroll
        for (int c = 0; c < 4; c++) {
            wreg[c]     = (ip0 + wiq0 * 4 + c < cnt) ? wc0[(size_t)c * NN] : 0.f;
            wreg[4 + c] = (ip0 + wiq1 * 4 + c < cnt) ? wc1[(size_t)c * NN] : 0.f;
        }
    };
    auto sts_w = [&](int buf) {
        *(float4*)(&sWT[buf][wkk][wiq0 * 4]) = make_float4(wreg[0], wreg[1], wreg[2], wreg[3]);
        *(float4*)(&sWT[buf][wkk][wiq1 * 4]) = make_float4(wreg[4], wreg[5], wreg[6], wreg[7]);
    };

    // prologue: tile 0 into buffer 0
    cp_h(0, 0);
    ldg_w(0);
    sts_w(0);

    float acc[4][4];
    #pragma unroll
    for (int a = 0; a < 4; a++)
        #pragma unroll
        for (int c = 0; c < 4; c++) acc[a][c] = 0.f;

    for (int kt = 0; kt < nt; kt++) {
        int buf = kt & 1;
        asm volatile("cp.async.wait_group 0;\n");   // H(kt) arrived
        __syncthreads();                            // tile kt visible; buf^1 readers retired

        bool more = (kt + 1 < nt);
        if (more) {
            cp_h(kt + 1, buf ^ 1);                  // async into other buffer
            ldg_w(kt + 1);                          // LDG in flight during compute
        }

        #pragma unroll
        for (int kk = 0; kk < 32; kk++) {
            float4 w4 = *(const float4*)(&sWT[buf][kk][ty * 4]);
            float4 hv = *(const float4*)(&sH[buf][kk][tx * 4]);
            acc[0][0] = fmaf(w4.x, hv.x, acc[0][0]);
            acc[0][1] = fmaf(w4.x, hv.y, acc[0][1]);
            acc[0][2] = fmaf(w4.x, hv.z, acc[0][2]);
            acc[0][3] = fmaf(w4.x, hv.w, acc[0][3]);
            acc[1][0] = fmaf(w4.y, hv.x, acc[1][0]);
            acc[1][1] = fmaf(w4.y, hv.y, acc[1][1]);
            acc[1][2] = fmaf(w4.y, hv.z, acc[1][2]);
            acc[1][3] = fmaf(w4.y, hv.w, acc[1][3]);
            acc[2][0] = fmaf(w4.z, hv.x, acc[2][0]);
            acc[2][1] = fmaf(w4.z, hv.y, acc[2][1]);
            acc[2][2] = fmaf(w4.z, hv.z, acc[2][2]);
            acc[2][3] = fmaf(w4.z, hv.w, acc[2][3]);
            acc[3][0] = fmaf(w4.w, hv.x, acc[3][0]);
            acc[3][1] = fmaf(w4.w, hv.y, acc[3][1]);
            acc[3][2] = fmaf(w4.w, hv.z, acc[3][2]);
            acc[3][3] = fmaf(w4.w, hv.w, acc[3][3]);
        }

        if (more) sts_w(buf ^ 1);                   // same safe window as cp_h
    }

    float inv = 1.0f / __uint_as_float(g_maxbits);
    #pragma unroll
    for (int a = 0; a < 4; a++) {
        int ipl = ty * 4 + a;
        if (ip0 + ipl < cnt) {
            int i = s_il[ipl];
            float* op = out + ((size_t)(b * NN + i)) * HH + hoff;
            *(float4*)(op + tx * 4) = make_float4(acc[a][0] * inv, acc[a][1] * inv,
                                                  acc[a][2] * inv, acc[a][3] * inv);
        }
    }
}

// ---------------------------------------------------------------------------
extern "C" void kernel_launch(void* const* d_in, const int* in_sizes, int n_in,
                              void* d_out, int out_size)
{
    const float* h_t    = (const float*)d_in[0];
    const int*   r_mat  = (const int*)  d_in[1];
    const float* d_mat  = (const float*)d_in[2];
    const float* mask   = (const float*)d_in[3];
    const int*   cog    = (const int*)  d_in[4];
    const float* domain = (const float*)d_in[5];
    float* out = (float*)d_out;

    k_compact<<<BB, NN>>>(mask);
    dim3 gz(NN / 8, BB);
    k_zero_inactive<<<gz, 256>>>(mask, out);
    dim3 g1(NN / 8, BB);
    k_build_w<<<g1, 128>>>(r_mat, d_mat, cog, domain);
    dim3 g2((NN / 64) * 2, BB);          // (i-tile, h-half) pairs
    k_gemm<<<g2, 256>>>(h_t, out);
}

// round 17
// speedup vs baseline: 1.2048x; 1.0358x over previous
#include <cuda_runtime.h>
#include <cstdint>

#define BB 64
#define NN 512
#define HH 128
#define NCOG 72
#define NRB 72

__device__ __align__(16) float g_wc[(size_t)BB * NN * NN];   // compacted w rows (~17MB, L2-resident)
__device__ int      g_jlist[BB][NN];
__device__ int      g_jcnt[BB];
__device__ unsigned g_maxbits;

// ---------------------------------------------------------------------------
__global__ void k_compact(const float* __restrict__ mask) {
    int b = blockIdx.x;
    int j = threadIdx.x;
    if (b == 0 && j == 0) g_maxbits = 0u;

    bool act = (mask[b * NN + j] != 0.0f);
    unsigned ball = __ballot_sync(0xffffffffu, act);

    __shared__ int wcnt[16], wbase[16];
    int warp = j >> 5, lane = j & 31;
    if (lane == 0) wcnt[warp] = __popc(ball);
    __syncthreads();
    if (j == 0) {
        int s = 0;
        for (int w = 0; w < 16; w++) { wbase[w] = s; s += wcnt[w]; }
        g_jcnt[b] = s;
    }
    __syncthreads();
    if (act) {
        int pos = wbase[warp] + __popc(ball & ((1u << lane) - 1u));
        g_jlist[b][pos] = j;
    }
}

// ---------------------------------------------------------------------------
// Build compacted w rows (R13/R15 staged version — dense int4/float4 reads,
// smem scatter staging, compact float4 writes; 8 rows/block; NO register
// row-pipeline: that variant measured ~1.9us slower).
// ---------------------------------------------------------------------------
__global__ void __launch_bounds__(128) k_build_w(
    const int*   __restrict__ rmat,
    const float* __restrict__ dmat,
    const int*   __restrict__ cog,
    const float* __restrict__ domain)
{
    int b   = blockIdx.y;
    int cnt = g_jcnt[b];
    int ip_base = blockIdx.x * 8;
    if (ip_base >= cnt) return;

    __shared__ int s_pos[NN];
    __shared__ __align__(16) float s_stage[NN];
    __shared__ int s_rows[8];
    __shared__ float smax[4];
    int t = threadIdx.x;

    #pragma unroll
    for (int q = 0; q < 4; q++) {
        s_pos[t + q * 128]   = -1;
        s_stage[t + q * 128] = 0.f;
    }
    __syncthreads();
    #pragma unroll
    for (int q = 0; q < 4; q++) {
        int jc = t + q * 128;
        if (jc < cnt) s_pos[g_jlist[b][jc]] = jc;
    }
    if (t < 8) {
        int ip = ip_base + t;
        s_rows[t] = (ip < cnt) ? g_jlist[b][ip] : -1;
    }
    __syncthreads();

    int cnt32 = (cnt + 31) & ~31;
    int nrows = min(8, cnt - ip_base);
    int j0 = t * 4;
    float lm = 0.f;

    for (int rr = 0; rr < nrows; rr++) {
        int i = s_rows[rr];
        size_t src = ((size_t)(b * NN + i)) * NN;

        int4   rv = *(const int4*)(rmat + src + j0);
        int4   cv = *(const int4*)(cog  + src + j0);
        float4 dv = *(const float4*)(dmat + src + j0);

        float w0 = fmaxf(__ldg(domain + cv.x * NRB + rv.x) - dv.x, 0.f);
        float w1 = fmaxf(__ldg(domain + cv.y * NRB + rv.y) - dv.y, 0.f);
        float w2 = fmaxf(__ldg(domain + cv.z * NRB + rv.z) - dv.z, 0.f);
        float w3 = fmaxf(__ldg(domain + cv.w * NRB + rv.w) - dv.w, 0.f);

        int p0 = s_pos[j0 + 0], p1 = s_pos[j0 + 1], p2 = s_pos[j0 + 2], p3 = s_pos[j0 + 3];
        if (p0 >= 0) { s_stage[p0] = w0; lm = fmaxf(lm, w0); }
        if (p1 >= 0) { s_stage[p1] = w1; lm = fmaxf(lm, w1); }
        if (p2 >= 0) { s_stage[p2] = w2; lm = fmaxf(lm, w2); }
        if (p3 >= 0) { s_stage[p3] = w3; lm = fmaxf(lm, w3); }
        __syncthreads();

        size_t dst = ((size_t)(b * NN + ip_base + rr)) * NN;
        if (j0 < cnt32)
            *(float4*)(g_wc + dst + j0) = *(const float4*)(s_stage + j0);
        __syncthreads();
    }

    #pragma unroll
    for (int off = 16; off; off >>= 1)
        lm = fmaxf(lm, __shfl_xor_sync(0xffffffffu, lm, off));
    if ((t & 31) == 0) smax[t >> 5] = lm;
    __syncthreads();
    if (t == 0) {
        float bm = fmaxf(fmaxf(smax[0], smax[1]), fmaxf(smax[2], smax[3]));
        atomicMax(&g_maxbits, __float_as_uint(bm));
    }
}

// ---------------------------------------------------------------------------
// H-split compacted GEMM, double-buffered (R16 structure). NEW: prologue
// zeros inactive output rows — each blockIdx.x slice (16 total) owns a
// 32-row stripe, so idle blocks (ip0 >= cnt) do the zeroing for free and
// k_zero_inactive is deleted.
// ---------------------------------------------------------------------------
__global__ void __launch_bounds__(256, 4) k_gemm(
    const float* __restrict__ h_t,
    const float* __restrict__ mask,
    float*       __restrict__ out)
{
    int b   = blockIdx.y;
    int cnt = g_jcnt[b];
    int bx  = blockIdx.x;
    int it  = bx >> 1;
    int hs  = bx & 1;
    int ip0 = it * 64;
    int tid = threadIdx.x;

    // Zero inactive rows in my 32-row stripe (grid.x = 16 covers all 512).
    {
        int r0 = bx * 32;
        int lane = tid & 31;
        float4 z = make_float4(0.f, 0.f, 0.f, 0.f);
        for (int rr = tid >> 5; rr < 32; rr += 8) {
            int row = r0 + rr;
            if (mask[b * NN + row] == 0.0f)
                ((float4*)(out + ((size_t)(b * NN + row)) * HH))[lane] = z;
        }
    }

    if (ip0 >= cnt) return;
    int hoff = hs * 64;
    int nt = (cnt + 31) >> 5;

    int tx  = tid & 15;
    int ty  = tid >> 4;

    __shared__ __align__(16) float sWT[2][32][68];
    __shared__ __align__(16) float sH[2][32][64];
    __shared__ int s_jl[NN];
    __shared__ int s_il[64];

    #pragma unroll
    for (int q = 0; q < 2; q++) {
        int jc = tid + q * 256;
        s_jl[jc] = (jc < cnt) ? g_jlist[b][jc] : 0;
    }
    if (tid < 64) {
        int ip = ip0 + tid;
        s_il[tid] = (ip < cnt) ? g_jlist[b][ip] : 0;
    }
    __syncthreads();   // s_jl ready

    const float* hb = h_t + (size_t)b * HH + hoff;
    const float* wb = g_wc + ((size_t)b * NN + ip0) * NN;

    int wkk  = tid & 31;
    int wiq0 = tid >> 5;             // 0..7
    int wiq1 = (tid + 256) >> 5;     // 8..15
    int hkk0 = tid >> 4,  hh4 = tid & 15;
    int hkk1 = (tid + 256) >> 4;

    float wreg[8];

    auto cp_h = [&](int kt, int buf) {
        int kc0 = kt * 32;
        int j0 = s_jl[kc0 + hkk0];
        int j1 = s_jl[kc0 + hkk1];
        uint32_t d0 = (uint32_t)__cvta_generic_to_shared(&sH[buf][hkk0][hh4 * 4]);
        uint32_t d1 = (uint32_t)__cvta_generic_to_shared(&sH[buf][hkk1][hh4 * 4]);
        const float* s0 = hb + (size_t)j0 * (BB * HH) + hh4 * 4;
        const float* s1 = hb + (size_t)j1 * (BB * HH) + hh4 * 4;
        asm volatile("cp.async.ca.shared.global [%0], [%1], 16;\n" :: "r"(d0), "l"(s0));
        asm volatile("cp.async.ca.shared.global [%0], [%1], 16;\n" :: "r"(d1), "l"(s1));
        asm volatile("cp.async.commit_group;\n");
    };
    auto ldg_w = [&](int kt) {
        int kc0 = kt * 32;
        const float* wc0 = wb + (size_t)(wiq0 * 4) * NN + kc0 + wkk;
        const float* wc1 = wb + (size_t)(wiq1 * 4) * NN + kc0 + wkk;
        #pragma unroll
        for (int c = 0; c < 4; c++) {
            wreg[c]     = (ip0 + wiq0 * 4 + c < cnt) ? wc0[(size_t)c * NN] : 0.f;
            wreg[4 + c] = (ip0 + wiq1 * 4 + c < cnt) ? wc1[(size_t)c * NN] : 0.f;
        }
    };
    auto sts_w = [&](int buf) {
        *(float4*)(&sWT[buf][wkk][wiq0 * 4]) = make_float4(wreg[0], wreg[1], wreg[2], wreg[3]);
        *(float4*)(&sWT[buf][wkk][wiq1 * 4]) = make_float4(wreg[4], wreg[5], wreg[6], wreg[7]);
    };

    cp_h(0, 0);
    ldg_w(0);
    sts_w(0);

    float acc[4][4];
    #pragma unroll
    for (int a = 0; a < 4; a++)
        #pragma unroll
        for (int c = 0; c < 4; c++) acc[a][c] = 0.f;

    for (int kt = 0; kt < nt; kt++) {
        int buf = kt & 1;
        asm volatile("cp.async.wait_group 0;\n");
        __syncthreads();

        bool more = (kt + 1 < nt);
        if (more) {
            cp_h(kt + 1, buf ^ 1);
            ldg_w(kt + 1);
        }

        #pragma unroll
        for (int kk = 0; kk < 32; kk++) {
            float4 w4 = *(const float4*)(&sWT[buf][kk][ty * 4]);
            float4 hv = *(const float4*)(&sH[buf][kk][tx * 4]);
            acc[0][0] = fmaf(w4.x, hv.x, acc[0][0]);
            acc[0][1] = fmaf(w4.x, hv.y, acc[0][1]);
            acc[0][2] = fmaf(w4.x, hv.z, acc[0][2]);
            acc[0][3] = fmaf(w4.x, hv.w, acc[0][3]);
            acc[1][0] = fmaf(w4.y, hv.x, acc[1][0]);
            acc[1][1] = fmaf(w4.y, hv.y, acc[1][1]);
            acc[1][2] = fmaf(w4.y, hv.z, acc[1][2]);
            acc[1][3] = fmaf(w4.y, hv.w, acc[1][3]);
            acc[2][0] = fmaf(w4.z, hv.x, acc[2][0]);
            acc[2][1] = fmaf(w4.z, hv.y, acc[2][1]);
            acc[2][2] = fmaf(w4.z, hv.z, acc[2][2]);
            acc[2][3] = fmaf(w4.z, hv.w, acc[2][3]);
            acc[3][0] = fmaf(w4.w, hv.x, acc[3][0]);
            acc[3][1] = fmaf(w4.w, hv.y, acc[3][1]);
            acc[3][2] = fmaf(w4.w, hv.z, acc[3][2]);
            acc[3][3] = fmaf(w4.w, hv.w, acc[3][3]);
        }

        if (more) sts_w(buf ^ 1);
    }

    float inv = 1.0f / __uint_as_float(g_maxbits);
    #pragma unroll
    for (int a = 0; a < 4; a++) {
        int ipl = ty * 4 + a;
        if (ip0 + ipl < cnt) {
            int i = s_il[ipl];
            float* op = out + ((size_t)(b * NN + i)) * HH + hoff;
            *(float4*)(op + tx * 4) = make_float4(acc[a][0] * inv, acc[a][1] * inv,
                                                  acc[a][2] * inv, acc[a][3] * inv);
        }
    }
}

// ---------------------------------------------------------------------------
extern "C" void kernel_launch(void* const* d_in, const int* in_sizes, int n_in,
                              void* d_out, int out_size)
{
    const float* h_t    = (const float*)d_in[0];
    const int*   r_mat  = (const int*)  d_in[1];
    const float* d_mat  = (const float*)d_in[2];
    const float* mask   = (const float*)d_in[3];
    const int*   cog    = (const int*)  d_in[4];
    const float* domain = (const float*)d_in[5];
    float* out = (float*)d_out;

    k_compact<<<BB, NN>>>(mask);
    dim3 g1(NN / 8, BB);
    k_build_w<<<g1, 128>>>(r_mat, d_mat, cog, domain);
    dim3 g2((NN / 64) * 2, BB);          // (i-tile, h-half) pairs
    k_gemm<<<g2, 256>>>(h_t, mask, out);
}